// round 3
// baseline (speedup 1.0000x reference)
#include <cuda_runtime.h>
#include <cstdint>
#include <cstddef>

// Problem dims
#define T_STEPS 256
#define B_DIM   512
#define E_DIM   256
#define A_DIM   7
#define M_DIM   200
#define S_DIM   30
#define H_DIM   200
#define EA_DIM  263
#define G3      600
#define TB      131072   // T*B

// Scratch (static device arrays: allocation-free rule)
__device__ float g_X[(size_t)TB * 200];   // X, later reused as P1
__device__ float g_GX[(size_t)TB * 600];  // precomputed input-side GRU gates
__device__ unsigned int g_bar;            // grid barrier counter

__device__ __forceinline__ float elu_f(float x) { return x > 0.f ? x : expm1f(x); }
__device__ __forceinline__ float sigm_f(float x) { return 1.f / (1.f + expf(-x)); }

// ---------------------------------------------------------------------------
// Tiled fp32 GEMM: C[rows,N] = act(A[rows,K] @ W[N,K]^T + bias)
// BM=128, BN=64, BK=16, 256 threads, 8x4 microtile.
// CONCAT=1: A is concat(A[rows,KS], A2[rows,K-KS]) along K.
// ---------------------------------------------------------------------------
template<int ACT, int CONCAT>
__global__ __launch_bounds__(256) void gemm_kernel(
    const float* __restrict__ A, const float* __restrict__ A2,
    int K, int KS,
    const float* __restrict__ W, const float* __restrict__ bias,
    float* __restrict__ C, int N)
{
    __shared__ float As[128][17];
    __shared__ float Ws[64][17];
    const int row0 = blockIdx.x * 128;
    const int col0 = blockIdx.y * 64;
    const int tid = threadIdx.x;
    const int tx = tid & 15;   // 0..15 -> 4 cols each
    const int ty = tid >> 4;   // 0..15 -> 8 rows each

    float acc[8][4];
#pragma unroll
    for (int i = 0; i < 8; i++)
#pragma unroll
        for (int j = 0; j < 4; j++) acc[i][j] = 0.f;

    for (int k0 = 0; k0 < K; k0 += 16) {
#pragma unroll
        for (int i = 0; i < 8; i++) {
            int idx = tid + i * 256;          // 2048 elements
            int r = idx >> 4, kk = idx & 15;
            int k = k0 + kk;
            float v = 0.f;
            if (k < K) {
                size_t grow = (size_t)(row0 + r);
                if (CONCAT)
                    v = (k < KS) ? A[grow * (size_t)KS + k]
                                 : A2[grow * (size_t)(K - KS) + (k - KS)];
                else
                    v = A[grow * (size_t)K + k];
            }
            As[r][kk] = v;
        }
#pragma unroll
        for (int i = 0; i < 4; i++) {
            int idx = tid + i * 256;          // 1024 elements
            int n = idx >> 4, kk = idx & 15;
            int k = k0 + kk;
            int gn = col0 + n;
            Ws[n][kk] = (k < K && gn < N) ? W[(size_t)gn * (size_t)K + k] : 0.f;
        }
        __syncthreads();
#pragma unroll
        for (int kk = 0; kk < 16; kk++) {
            float a[8], w[4];
#pragma unroll
            for (int i = 0; i < 8; i++) a[i] = As[ty * 8 + i][kk];
#pragma unroll
            for (int j = 0; j < 4; j++) w[j] = Ws[tx * 4 + j][kk];
#pragma unroll
            for (int i = 0; i < 8; i++)
#pragma unroll
                for (int j = 0; j < 4; j++) acc[i][j] = fmaf(a[i], w[j], acc[i][j]);
        }
        __syncthreads();
    }

#pragma unroll
    for (int i = 0; i < 8; i++) {
        int gr = row0 + ty * 8 + i;
#pragma unroll
        for (int j = 0; j < 4; j++) {
            int gc = col0 + tx * 4 + j;
            if (gc < N) {
                float v = acc[i][j] + bias[gc];
                if (ACT) v = elu_f(v);
                C[(size_t)gr * (size_t)N + gc] = v;
            }
        }
    }
}

// ---------------------------------------------------------------------------
// Recurrent scan: 128 persistent blocks = 16 batch-chunks(32) x 8 m-chunks(25).
// Each block keeps its Whh slice (75 rows x 200) in SMEM for all 256 steps.
// Grid-wide step sync via a monotonic atomic counter (blocks co-resident).
// ---------------------------------------------------------------------------
#define SC_C   8
#define SC_R   16
#define SC_MC  25
#define SC_BC  32
#define SC_ROWS 75
#define SC_THREADS 120  // 15 row-groups(5 rows) x 8 batch-groups(4 b)
#define SC_SMEM_FLOATS (SC_ROWS*200 + SC_BC*200 + SC_ROWS*SC_BC)

__global__ void init_bar_kernel() { g_bar = 0u; }

__global__ __launch_bounds__(SC_THREADS) void scan_kernel(
    const float* __restrict__ GX, const float* __restrict__ Whh,
    const float* __restrict__ bhh, const float* __restrict__ in_state,
    const unsigned char* __restrict__ reset, float* __restrict__ states)
{
    extern __shared__ float sm[];
    float* sW  = sm;                      // [75][200]  Whh slice (persistent)
    float* sH  = sm + SC_ROWS * 200;      // [32][200]  h for this batch chunk
    float* sGH = sH + SC_BC * 200;        // [75][32]   gh results

    const int c   = blockIdx.x & 7;
    const int r   = blockIdx.x >> 3;
    const int tid = threadIdx.x;
    const int rg  = tid >> 3;   // 0..14 -> 5 gh-rows each
    const int bg  = tid & 7;    // 0..7  -> 4 batch rows each
    const unsigned int nb = gridDim.x;

    // Load Whh slice once: local row lr -> gate g=lr/25, j=lr%25 -> global row g*200 + c*25 + j
    for (int idx = tid; idx < SC_ROWS * 200; idx += SC_THREADS) {
        int lr = idx / 200, k = idx % 200;
        int g = lr / SC_MC, j = lr % SC_MC;
        int grow = g * 200 + c * SC_MC + j;
        sW[idx] = Whh[(size_t)grow * 200 + k];
    }

    for (int t = 0; t < T_STEPS; t++) {
        const float* hsrc = (t == 0) ? in_state
                                     : (states + (size_t)(t - 1) * B_DIM * M_DIM);
        for (int idx = tid; idx < SC_BC * 200; idx += SC_THREADS) {
            int bl = idx / 200, k = idx % 200;
            int b = r * SC_BC + bl;
            float v = __ldcg(&hsrc[(size_t)b * 200 + k]);
            if (reset[t * B_DIM + b]) v = 0.f;
            sH[idx] = v;
        }
        __syncthreads();

        // mini-GEMM: gh[75,32] = Whh_slice[75,200] @ h[32,200]^T
        float acc[5][4];
#pragma unroll
        for (int i = 0; i < 5; i++)
#pragma unroll
            for (int j = 0; j < 4; j++) acc[i][j] = 0.f;
        for (int k = 0; k < 200; k += 4) {
            float4 w[5], h[4];
#pragma unroll
            for (int i = 0; i < 5; i++)
                w[i] = *(const float4*)(sW + (rg * 5 + i) * 200 + k);
#pragma unroll
            for (int j = 0; j < 4; j++)
                h[j] = *(const float4*)(sH + (bg * 4 + j) * 200 + k);
#pragma unroll
            for (int i = 0; i < 5; i++)
#pragma unroll
                for (int j = 0; j < 4; j++) {
                    acc[i][j] = fmaf(w[i].x, h[j].x, acc[i][j]);
                    acc[i][j] = fmaf(w[i].y, h[j].y, acc[i][j]);
                    acc[i][j] = fmaf(w[i].z, h[j].z, acc[i][j]);
                    acc[i][j] = fmaf(w[i].w, h[j].w, acc[i][j]);
                }
        }
#pragma unroll
        for (int i = 0; i < 5; i++)
#pragma unroll
            for (int j = 0; j < 4; j++)
                sGH[(rg * 5 + i) * SC_BC + bg * 4 + j] = acc[i][j];
        __syncthreads();

        // GRU elementwise for (25 m x 32 b) of this block
        size_t gbase = (size_t)(t * B_DIM) * G3;
        for (int idx = tid; idx < SC_MC * SC_BC; idx += SC_THREADS) {
            int bl = idx / SC_MC, j = idx % SC_MC;   // j-inner: coalesced GX reads
            int b = r * SC_BC + bl;
            int m = c * SC_MC + j;
            size_t gxi = gbase + (size_t)b * G3 + m;
            float xr = GX[gxi];
            float xz = GX[gxi + 200];
            float xn = GX[gxi + 400];
            float hr = sGH[j * SC_BC + bl]                + bhh[m];
            float hz = sGH[(SC_MC + j) * SC_BC + bl]      + bhh[200 + m];
            float hn = sGH[(2 * SC_MC + j) * SC_BC + bl]  + bhh[400 + m];
            float rgate = sigm_f(xr + hr);
            float z     = sigm_f(xz + hz);
            float n     = tanhf(xn + rgate * hn);
            float hp    = sH[bl * 200 + m];
            float hnew  = (1.f - z) * n + z * hp;
            states[(size_t)t * B_DIM * M_DIM + (size_t)b * M_DIM + m] = hnew;
        }
        __threadfence();
        __syncthreads();
        if (tid == 0) {
            atomicAdd(&g_bar, 1u);
            unsigned int target = nb * (unsigned int)(t + 1);
            while (*(volatile unsigned int*)&g_bar < target) { }
        }
        __syncthreads();
        __threadfence();
    }
}

// ---------------------------------------------------------------------------
// Sample head: reproduce jax.random.normal(key(42), (512,30)) with the
// PARTITIONABLE threefry path (jax_threefry_partitionable=True default since
// jax 0.4.36): per linear element i, counter = uint64(i) -> x=(hi,lo)=(0,i),
// run threefry2x32 with key (0,42), bits = out0 ^ out1. Then
// u = max(lo, bits_to_[0,1) * 2 + lo), noise = sqrt(2)*erfinv(u),
// sample = mean + (softplus(std_raw)+0.1)*noise.
// ---------------------------------------------------------------------------
__global__ void sample_kernel(const float* __restrict__ posts_last,
                              float* __restrict__ out)
{
    int i = blockIdx.x * blockDim.x + threadIdx.x;
    const int NTOT = B_DIM * S_DIM;      // 15360
    if (i >= NTOT) return;

    // threefry2x32(key=(0,42), x=(0, i)) — partitionable counter scheme
    uint32_t x0 = 0u, x1 = (uint32_t)i;
    const uint32_t ks0 = 0u, ks1 = 42u, ks2 = 0u ^ 42u ^ 0x1BD11BDAu;
    x0 += ks0; x1 += ks1;
#define TF_RND(rot) { x0 += x1; x1 = (x1 << (rot)) | (x1 >> (32 - (rot))); x1 ^= x0; }
    TF_RND(13) TF_RND(15) TF_RND(26) TF_RND(6)   x0 += ks1; x1 += ks2 + 1u;
    TF_RND(17) TF_RND(29) TF_RND(16) TF_RND(24)  x0 += ks2; x1 += ks0 + 2u;
    TF_RND(13) TF_RND(15) TF_RND(26) TF_RND(6)   x0 += ks0; x1 += ks1 + 3u;
    TF_RND(17) TF_RND(29) TF_RND(16) TF_RND(24)  x0 += ks1; x1 += ks2 + 4u;
    TF_RND(13) TF_RND(15) TF_RND(26) TF_RND(6)   x0 += ks2; x1 += ks0 + 5u;
#undef TF_RND
    uint32_t bits = x0 ^ x1;   // 32-bit draw combines both output words

    // jax uniform(lo=nextafter(-1,0), hi=1): (hi-lo) rounds to 2.0f in fp32
    float f = __uint_as_float((bits >> 9) | 0x3F800000u) - 1.0f;
    const float lo = -0.99999994f;
    float u = fmaxf(lo, f * 2.0f + lo);
    float noise = 1.41421356f * erfinvf(u);

    int b = i / S_DIM, s = i % S_DIM;
    float mean = posts_last[(size_t)b * 60 + s];
    float sraw = posts_last[(size_t)b * 60 + 30 + s];
    float stdv = fmaxf(sraw, 0.f) + log1pf(expf(-fabsf(sraw))) + 0.1f; // softplus + MIN_STD
    out[i] = mean + stdv * noise;
}

// ---------------------------------------------------------------------------
extern "C" void kernel_launch(void* const* d_in, const int* in_sizes, int n_in,
                              void* d_out, int out_size)
{
    const float* embed    = (const float*)d_in[0];
    const float* action   = (const float*)d_in[1];
    const unsigned char* reset = (const unsigned char*)d_in[2];
    const float* in_state = (const float*)d_in[3];
    const float* W1 = (const float*)d_in[4];
    const float* b1 = (const float*)d_in[5];
    const float *Wih, *bih, *Whh, *bhh;
    if (in_sizes[7] == 600) {          // dict order: Wih, bih, Whh, bhh
        Wih = (const float*)d_in[6]; bih = (const float*)d_in[7];
        Whh = (const float*)d_in[8]; bhh = (const float*)d_in[9];
    } else {                           // signature order: Wih, Whh, bih, bhh
        Wih = (const float*)d_in[6]; Whh = (const float*)d_in[7];
        bih = (const float*)d_in[8]; bhh = (const float*)d_in[9];
    }
    const float* W2 = (const float*)d_in[10];
    const float* b2 = (const float*)d_in[11];
    const float* W3 = (const float*)d_in[12];
    const float* b3 = (const float*)d_in[13];

    float* out    = (float*)d_out;
    float* sample = out;                                  // [512,30]
    float* states = out + (size_t)B_DIM * S_DIM;          // [256,512,200]
    float* posts  = states + (size_t)T_STEPS * B_DIM * M_DIM; // [256,512,60]

    float* Xbuf; cudaGetSymbolAddress((void**)&Xbuf, g_X);
    float* GXbuf; cudaGetSymbolAddress((void**)&GXbuf, g_GX);

    // K1: X = elu([embed,action] @ W1^T + b1)   [131072,263]x[263,200]
    gemm_kernel<1, 1><<<dim3(TB / 128, 4), 256>>>(
        embed, action, EA_DIM, E_DIM, W1, b1, Xbuf, H_DIM);

    // K2: GX = X @ Wih^T + bih                  [131072,200]x[200,600]
    gemm_kernel<0, 0><<<dim3(TB / 128, 10), 256>>>(
        Xbuf, nullptr, H_DIM, 0, Wih, bih, GXbuf, G3);

    // K3: recurrent scan -> states
    init_bar_kernel<<<1, 1>>>();
    cudaFuncSetAttribute(scan_kernel,
                         cudaFuncAttributeMaxDynamicSharedMemorySize,
                         SC_SMEM_FLOATS * (int)sizeof(float));
    scan_kernel<<<SC_C * SC_R, SC_THREADS, SC_SMEM_FLOATS * sizeof(float)>>>(
        GXbuf, Whh, bhh, in_state, reset, states);

    // K4: P1 = elu(states @ W2^T + b2)  (reuse g_X)
    gemm_kernel<1, 0><<<dim3(TB / 128, 4), 256>>>(
        states, nullptr, M_DIM, 0, W2, b2, Xbuf, H_DIM);

    // K5: posts = P1 @ W3^T + b3
    gemm_kernel<0, 0><<<dim3(TB / 128, 1), 256>>>(
        Xbuf, nullptr, H_DIM, 0, W3, b3, posts, 2 * S_DIM);

    // K6: sample from posts[-1] with partitionable-threefry noise
    const float* posts_last = posts + (size_t)(T_STEPS - 1) * B_DIM * 2 * S_DIM;
    sample_kernel<<<(B_DIM * S_DIM + 255) / 256, 256>>>(posts_last, sample);
}

// round 4
// speedup vs baseline: 1.0661x; 1.0661x over previous
#include <cuda_runtime.h>
#include <cstdint>
#include <cstddef>

// Problem dims
#define T_STEPS 256
#define B_DIM   512
#define E_DIM   256
#define A_DIM   7
#define M_DIM   200
#define S_DIM   30
#define H_DIM   200
#define EA_DIM  263
#define G3      600
#define TB      131072   // T*B

typedef unsigned long long ull;

// Scratch (static device arrays: allocation-free rule)
__device__ float g_X[(size_t)TB * 200];   // X, later reused as P1
__device__ float g_GX[(size_t)TB * 600];  // precomputed input-side GRU gates
__device__ unsigned int g_bar;            // grid barrier counter

__device__ __forceinline__ float elu_f(float x) { return x > 0.f ? x : expm1f(x); }
__device__ __forceinline__ float sigm_f(float x) { return 1.f / (1.f + expf(-x)); }

// Packed f32x2 helpers (Blackwell FFMA2 — 2x fp32 FMA throughput)
__device__ __forceinline__ void fma2(ull& d, ull a, ull b) {
    asm("fma.rn.f32x2 %0, %1, %2, %3;" : "=l"(d) : "l"(a), "l"(b), "l"(d));
}
__device__ __forceinline__ ull pack2(float x, float y) {
    ull r;
    asm("mov.b64 %0, {%1, %2};" : "=l"(r)
        : "r"(__float_as_uint(x)), "r"(__float_as_uint(y)));
    return r;
}
__device__ __forceinline__ void unpack2(ull v, float& lo, float& hi) {
    unsigned int a, b;
    asm("mov.b64 {%0, %1}, %2;" : "=r"(a), "=r"(b) : "l"(v));
    lo = __uint_as_float(a); hi = __uint_as_float(b);
}

// ---------------------------------------------------------------------------
// f32x2 tiled GEMM: C[rows,N] = act(A[rows,K] @ W[N,K]^T + bias)
// BM=128, BN=64, BK=16, 256 threads. Microtile 8 rows x 4 cols, accumulators
// packed as f32x2 over row pairs. A smem transposed [kk][M] so row-pairs load
// directly as 64-bit words. Next K-tile prefetched into registers during FMA.
// ---------------------------------------------------------------------------
#define GBM 128
#define GBN 64
#define GBK 16
#define ASTR 132   // padded M-stride (multiple of 4 floats, breaks bank conflicts)
#define WSTR 68    // padded N-stride

template<int ACT, int CONCAT>
__global__ __launch_bounds__(256) void gemm_kernel(
    const float* __restrict__ A, const float* __restrict__ A2,
    int K, int KS,
    const float* __restrict__ W, const float* __restrict__ bias,
    float* __restrict__ C, int N)
{
    __shared__ float As[GBK * ASTR];   // As[kk][r]
    __shared__ float Ws[GBK * WSTR];   // Ws[kk][n]

    const int row0 = blockIdx.x * GBM;
    const int col0 = blockIdx.y * GBN;
    const int tid = threadIdx.x;
    const int tx = tid & 15;   // 0..15 -> 4 cols each
    const int ty = tid >> 4;   // 0..15 -> 8 rows each

    // Loader mapping: lk = k-offset within tile, lr0/ln0 = row/col base
    const int lk  = tid & 15;
    const int lr0 = tid >> 4;   // + 16*i, i<8  -> 128 rows
    const int ln0 = tid >> 4;   // + 16*i, i<4  -> 64 cols

    ull acc[4][4];
#pragma unroll
    for (int i = 0; i < 4; i++)
#pragma unroll
        for (int j = 0; j < 4; j++) acc[i][j] = 0ull;

    float ra[8], rw[4];

    // Prologue: load tile k0=0 into registers
    {
        int k = lk;
#pragma unroll
        for (int i = 0; i < 8; i++) {
            float v = 0.f;
            if (k < K) {
                size_t grow = (size_t)(row0 + lr0 + 16 * i);
                if (CONCAT)
                    v = (k < KS) ? A[grow * (size_t)KS + k]
                                 : A2[grow * (size_t)(K - KS) + (k - KS)];
                else
                    v = A[grow * (size_t)K + k];
            }
            ra[i] = v;
        }
#pragma unroll
        for (int i = 0; i < 4; i++) {
            int gn = col0 + ln0 + 16 * i;
            rw[i] = (k < K && gn < N) ? W[(size_t)gn * (size_t)K + k] : 0.f;
        }
    }

    for (int k0 = 0; k0 < K; k0 += GBK) {
        __syncthreads();   // previous compute done before overwriting smem
#pragma unroll
        for (int i = 0; i < 8; i++) As[lk * ASTR + lr0 + 16 * i] = ra[i];
#pragma unroll
        for (int i = 0; i < 4; i++) Ws[lk * WSTR + ln0 + 16 * i] = rw[i];
        __syncthreads();

        // Prefetch next tile into registers (overlaps with FMA below)
        if (k0 + GBK < K) {
            int k = k0 + GBK + lk;
#pragma unroll
            for (int i = 0; i < 8; i++) {
                float v = 0.f;
                if (k < K) {
                    size_t grow = (size_t)(row0 + lr0 + 16 * i);
                    if (CONCAT)
                        v = (k < KS) ? A[grow * (size_t)KS + k]
                                     : A2[grow * (size_t)(K - KS) + (k - KS)];
                    else
                        v = A[grow * (size_t)K + k];
                }
                ra[i] = v;
            }
#pragma unroll
            for (int i = 0; i < 4; i++) {
                int gn = col0 + ln0 + 16 * i;
                rw[i] = (k < K && gn < N) ? W[(size_t)gn * (size_t)K + k] : 0.f;
            }
        }

        // Compute on current smem tile
#pragma unroll
        for (int kk = 0; kk < GBK; kk++) {
            const ull* ap = (const ull*)(As + kk * ASTR + ty * 8);  // 4 row-pairs
            ull a2[4];
#pragma unroll
            for (int i = 0; i < 4; i++) a2[i] = ap[i];
            const float4 wv = *(const float4*)(Ws + kk * WSTR + tx * 4);
            ull w2[4];
            w2[0] = pack2(wv.x, wv.x);
            w2[1] = pack2(wv.y, wv.y);
            w2[2] = pack2(wv.z, wv.z);
            w2[3] = pack2(wv.w, wv.w);
#pragma unroll
            for (int i = 0; i < 4; i++)
#pragma unroll
                for (int j = 0; j < 4; j++) fma2(acc[i][j], a2[i], w2[j]);
        }
    }

    // Epilogue: bias + activation + vectorized stores
    const int gc0 = col0 + tx * 4;
    float bv[4];
#pragma unroll
    for (int j = 0; j < 4; j++) bv[j] = (gc0 + j < N) ? bias[gc0 + j] : 0.f;

#pragma unroll
    for (int i = 0; i < 4; i++) {
        float vlo[4], vhi[4];
#pragma unroll
        for (int j = 0; j < 4; j++) {
            float lo, hi;
            unpack2(acc[i][j], lo, hi);
            lo += bv[j]; hi += bv[j];
            if (ACT) { lo = elu_f(lo); hi = elu_f(hi); }
            vlo[j] = lo; vhi[j] = hi;
        }
        size_t gr0 = (size_t)(row0 + ty * 8 + 2 * i);
        if (gc0 + 3 < N) {
            *(float4*)(C + gr0 * (size_t)N + gc0)       = make_float4(vlo[0], vlo[1], vlo[2], vlo[3]);
            *(float4*)(C + (gr0 + 1) * (size_t)N + gc0) = make_float4(vhi[0], vhi[1], vhi[2], vhi[3]);
        } else {
#pragma unroll
            for (int j = 0; j < 4; j++) {
                if (gc0 + j < N) {
                    C[gr0 * (size_t)N + gc0 + j]       = vlo[j];
                    C[(gr0 + 1) * (size_t)N + gc0 + j] = vhi[j];
                }
            }
        }
    }
}

// ---------------------------------------------------------------------------
// Recurrent scan: 128 persistent blocks = 16 batch-chunks(32) x 8 m-chunks(25).
// Each block keeps its Whh slice (75 rows x 200) in SMEM for all 256 steps.
// Grid-wide step sync via a monotonic atomic counter (blocks co-resident).
// Mini-GEMM inner loop uses f32x2 packed along K (adjacent in smem).
// ---------------------------------------------------------------------------
#define SC_C   8
#define SC_R   16
#define SC_MC  25
#define SC_BC  32
#define SC_ROWS 75
#define SC_THREADS 120  // 15 row-groups(5 rows) x 8 batch-groups(4 b)
#define SC_SMEM_FLOATS (SC_ROWS*200 + SC_BC*200 + SC_ROWS*SC_BC)

__global__ void init_bar_kernel() { g_bar = 0u; }

__global__ __launch_bounds__(SC_THREADS) void scan_kernel(
    const float* __restrict__ GX, const float* __restrict__ Whh,
    const float* __restrict__ bhh, const float* __restrict__ in_state,
    const unsigned char* __restrict__ reset, float* __restrict__ states)
{
    extern __shared__ float sm[];
    float* sW  = sm;                      // [75][200]  Whh slice (persistent)
    float* sH  = sm + SC_ROWS * 200;      // [32][200]  h for this batch chunk
    float* sGH = sH + SC_BC * 200;        // [75][32]   gh results

    const int c   = blockIdx.x & 7;
    const int r   = blockIdx.x >> 3;
    const int tid = threadIdx.x;
    const int rg  = tid >> 3;   // 0..14 -> 5 gh-rows each
    const int bg  = tid & 7;    // 0..7  -> 4 batch rows each
    const unsigned int nb = gridDim.x;

    // Load Whh slice once: local row lr -> gate g=lr/25, j=lr%25 -> global row g*200 + c*25 + j
    for (int idx = tid; idx < SC_ROWS * 200; idx += SC_THREADS) {
        int lr = idx / 200, k = idx % 200;
        int g = lr / SC_MC, j = lr % SC_MC;
        int grow = g * 200 + c * SC_MC + j;
        sW[idx] = Whh[(size_t)grow * 200 + k];
    }

    for (int t = 0; t < T_STEPS; t++) {
        const float* hsrc = (t == 0) ? in_state
                                     : (states + (size_t)(t - 1) * B_DIM * M_DIM);
        for (int idx = tid; idx < SC_BC * 200; idx += SC_THREADS) {
            int bl = idx / 200, k = idx % 200;
            int b = r * SC_BC + bl;
            float v = __ldcg(&hsrc[(size_t)b * 200 + k]);
            if (reset[t * B_DIM + b]) v = 0.f;
            sH[idx] = v;
        }
        __syncthreads();

        // mini-GEMM: gh[75,32] = Whh_slice[75,200] @ h[32,200]^T  (f32x2 over K)
        ull acc[5][4];
#pragma unroll
        for (int i = 0; i < 5; i++)
#pragma unroll
            for (int j = 0; j < 4; j++) acc[i][j] = 0ull;

#pragma unroll 2
        for (int k = 0; k < 200; k += 4) {
            ull w0[5], w1[5], h0[4], h1[4];
#pragma unroll
            for (int i = 0; i < 5; i++) {
                const ull* wp = (const ull*)(sW + (rg * 5 + i) * 200 + k);
                w0[i] = wp[0]; w1[i] = wp[1];
            }
#pragma unroll
            for (int j = 0; j < 4; j++) {
                const ull* hp = (const ull*)(sH + (bg * 4 + j) * 200 + k);
                h0[j] = hp[0]; h1[j] = hp[1];
            }
#pragma unroll
            for (int i = 0; i < 5; i++)
#pragma unroll
                for (int j = 0; j < 4; j++) {
                    fma2(acc[i][j], w0[i], h0[j]);
                    fma2(acc[i][j], w1[i], h1[j]);
                }
        }
#pragma unroll
        for (int i = 0; i < 5; i++)
#pragma unroll
            for (int j = 0; j < 4; j++) {
                float lo, hi;
                unpack2(acc[i][j], lo, hi);
                sGH[(rg * 5 + i) * SC_BC + bg * 4 + j] = lo + hi;
            }
        __syncthreads();

        // GRU elementwise for (25 m x 32 b) of this block
        size_t gbase = (size_t)(t * B_DIM) * G3;
        for (int idx = tid; idx < SC_MC * SC_BC; idx += SC_THREADS) {
            int bl = idx / SC_MC, j = idx % SC_MC;   // j-inner: coalesced GX reads
            int b = r * SC_BC + bl;
            int m = c * SC_MC + j;
            size_t gxi = gbase + (size_t)b * G3 + m;
            float xr = GX[gxi];
            float xz = GX[gxi + 200];
            float xn = GX[gxi + 400];
            float hr = sGH[j * SC_BC + bl]                + bhh[m];
            float hz = sGH[(SC_MC + j) * SC_BC + bl]      + bhh[200 + m];
            float hn = sGH[(2 * SC_MC + j) * SC_BC + bl]  + bhh[400 + m];
            float rgate = sigm_f(xr + hr);
            float z     = sigm_f(xz + hz);
            float n     = tanhf(xn + rgate * hn);
            float hp    = sH[bl * 200 + m];
            float hnew  = (1.f - z) * n + z * hp;
            states[(size_t)t * B_DIM * M_DIM + (size_t)b * M_DIM + m] = hnew;
        }
        __threadfence();
        __syncthreads();
        if (tid == 0) {
            atomicAdd(&g_bar, 1u);
            unsigned int target = nb * (unsigned int)(t + 1);
            while (*(volatile unsigned int*)&g_bar < target) { }
        }
        __syncthreads();
        __threadfence();
    }
}

// ---------------------------------------------------------------------------
// Sample head: partitionable threefry (counter = linear index), bits = o0^o1.
// ---------------------------------------------------------------------------
__global__ void sample_kernel(const float* __restrict__ posts_last,
                              float* __restrict__ out)
{
    int i = blockIdx.x * blockDim.x + threadIdx.x;
    const int NTOT = B_DIM * S_DIM;      // 15360
    if (i >= NTOT) return;

    // threefry2x32(key=(0,42), x=(0, i)) — partitionable counter scheme
    uint32_t x0 = 0u, x1 = (uint32_t)i;
    const uint32_t ks0 = 0u, ks1 = 42u, ks2 = 0u ^ 42u ^ 0x1BD11BDAu;
    x0 += ks0; x1 += ks1;
#define TF_RND(rot) { x0 += x1; x1 = (x1 << (rot)) | (x1 >> (32 - (rot))); x1 ^= x0; }
    TF_RND(13) TF_RND(15) TF_RND(26) TF_RND(6)   x0 += ks1; x1 += ks2 + 1u;
    TF_RND(17) TF_RND(29) TF_RND(16) TF_RND(24)  x0 += ks2; x1 += ks0 + 2u;
    TF_RND(13) TF_RND(15) TF_RND(26) TF_RND(6)   x0 += ks0; x1 += ks1 + 3u;
    TF_RND(17) TF_RND(29) TF_RND(16) TF_RND(24)  x0 += ks1; x1 += ks2 + 4u;
    TF_RND(13) TF_RND(15) TF_RND(26) TF_RND(6)   x0 += ks2; x1 += ks0 + 5u;
#undef TF_RND
    uint32_t bits = x0 ^ x1;   // 32-bit draw combines both output words

    // jax uniform(lo=nextafter(-1,0), hi=1): (hi-lo) rounds to 2.0f in fp32
    float f = __uint_as_float((bits >> 9) | 0x3F800000u) - 1.0f;
    const float lo = -0.99999994f;
    float u = fmaxf(lo, f * 2.0f + lo);
    float noise = 1.41421356f * erfinvf(u);

    int b = i / S_DIM, s = i % S_DIM;
    float mean = posts_last[(size_t)b * 60 + s];
    float sraw = posts_last[(size_t)b * 60 + 30 + s];
    float stdv = fmaxf(sraw, 0.f) + log1pf(expf(-fabsf(sraw))) + 0.1f; // softplus + MIN_STD
    out[i] = mean + stdv * noise;
}

// ---------------------------------------------------------------------------
extern "C" void kernel_launch(void* const* d_in, const int* in_sizes, int n_in,
                              void* d_out, int out_size)
{
    const float* embed    = (const float*)d_in[0];
    const float* action   = (const float*)d_in[1];
    const unsigned char* reset = (const unsigned char*)d_in[2];
    const float* in_state = (const float*)d_in[3];
    const float* W1 = (const float*)d_in[4];
    const float* b1 = (const float*)d_in[5];
    const float *Wih, *bih, *Whh, *bhh;
    if (in_sizes[7] == 600) {          // dict order: Wih, bih, Whh, bhh
        Wih = (const float*)d_in[6]; bih = (const float*)d_in[7];
        Whh = (const float*)d_in[8]; bhh = (const float*)d_in[9];
    } else {                           // signature order: Wih, Whh, bih, bhh
        Wih = (const float*)d_in[6]; Whh = (const float*)d_in[7];
        bih = (const float*)d_in[8]; bhh = (const float*)d_in[9];
    }
    const float* W2 = (const float*)d_in[10];
    const float* b2 = (const float*)d_in[11];
    const float* W3 = (const float*)d_in[12];
    const float* b3 = (const float*)d_in[13];

    float* out    = (float*)d_out;
    float* sample = out;                                  // [512,30]
    float* states = out + (size_t)B_DIM * S_DIM;          // [256,512,200]
    float* posts  = states + (size_t)T_STEPS * B_DIM * M_DIM; // [256,512,60]

    float* Xbuf; cudaGetSymbolAddress((void**)&Xbuf, g_X);
    float* GXbuf; cudaGetSymbolAddress((void**)&GXbuf, g_GX);

    // K1: X = elu([embed,action] @ W1^T + b1)   [131072,263]x[263,200]
    gemm_kernel<1, 1><<<dim3(TB / 128, 4), 256>>>(
        embed, action, EA_DIM, E_DIM, W1, b1, Xbuf, H_DIM);

    // K2: GX = X @ Wih^T + bih                  [131072,200]x[200,600]
    gemm_kernel<0, 0><<<dim3(TB / 128, 10), 256>>>(
        Xbuf, nullptr, H_DIM, 0, Wih, bih, GXbuf, G3);

    // K3: recurrent scan -> states
    init_bar_kernel<<<1, 1>>>();
    cudaFuncSetAttribute(scan_kernel,
                         cudaFuncAttributeMaxDynamicSharedMemorySize,
                         SC_SMEM_FLOATS * (int)sizeof(float));
    scan_kernel<<<SC_C * SC_R, SC_THREADS, SC_SMEM_FLOATS * sizeof(float)>>>(
        GXbuf, Whh, bhh, in_state, reset, states);

    // K4: P1 = elu(states @ W2^T + b2)  (reuse g_X)
    gemm_kernel<1, 0><<<dim3(TB / 128, 4), 256>>>(
        states, nullptr, M_DIM, 0, W2, b2, Xbuf, H_DIM);

    // K5: posts = P1 @ W3^T + b3
    gemm_kernel<0, 0><<<dim3(TB / 128, 1), 256>>>(
        Xbuf, nullptr, H_DIM, 0, W3, b3, posts, 2 * S_DIM);

    // K6: sample from posts[-1] with partitionable-threefry noise
    const float* posts_last = posts + (size_t)(T_STEPS - 1) * B_DIM * 2 * S_DIM;
    sample_kernel<<<(B_DIM * S_DIM + 255) / 256, 256>>>(posts_last, sample);
}

// round 5
// speedup vs baseline: 1.3187x; 1.2370x over previous
#include <cuda_runtime.h>
#include <cstdint>
#include <cstddef>

// Problem dims
#define T_STEPS 256
#define B_DIM   512
#define E_DIM   256
#define A_DIM   7
#define M_DIM   200
#define S_DIM   30
#define H_DIM   200
#define EA_DIM  263
#define G3      600
#define TB      131072   // T*B

typedef unsigned long long ull;

// Scratch (static device arrays: allocation-free rule)
__device__ float g_X[(size_t)TB * 200];   // X, later reused as P1
__device__ float g_GX[(size_t)TB * 600];  // precomputed input-side GRU gates
__device__ unsigned int g_bar;            // grid barrier counter

__device__ __forceinline__ float elu_f(float x) { return x > 0.f ? x : expm1f(x); }
__device__ __forceinline__ float sigm_f(float x) { return 1.f / (1.f + expf(-x)); }

// Packed f32x2 helpers (Blackwell FFMA2 — 2x fp32 FMA throughput)
__device__ __forceinline__ void fma2(ull& d, ull a, ull b) {
    asm("fma.rn.f32x2 %0, %1, %2, %3;" : "=l"(d) : "l"(a), "l"(b), "l"(d));
}
__device__ __forceinline__ ull pack2(float x, float y) {
    ull r;
    asm("mov.b64 %0, {%1, %2};" : "=l"(r)
        : "r"(__float_as_uint(x)), "r"(__float_as_uint(y)));
    return r;
}
__device__ __forceinline__ void unpack2(ull v, float& lo, float& hi) {
    unsigned int a, b;
    asm("mov.b64 {%0, %1}, %2;" : "=r"(a), "=r"(b) : "l"(v));
    lo = __uint_as_float(a); hi = __uint_as_float(b);
}

// ---------------------------------------------------------------------------
// f32x2 tiled GEMM with 2-stage smem double buffer.
// C[rows,N] = act(A[rows,K] @ W[N,K]^T + bias)
// BM=128, BN=64, BK=16, 256 threads, microtile 8 rows x 4 cols (f32x2 over
// row pairs). Global loads are float4; tile t+1 LDGs are issued before tile t
// compute so compute covers L2 latency. __launch_bounds__(256,2) pins regs.
// ---------------------------------------------------------------------------
#define GBM 128
#define GBN 64
#define GBK 16
#define ASTR 132
#define WSTR 68

template<int CONCAT>
__device__ __forceinline__ float4 loadA4(const float* __restrict__ A,
                                         const float* __restrict__ A2,
                                         size_t row, int k, int K, int KS)
{
    float4 v = make_float4(0.f, 0.f, 0.f, 0.f);
    if (CONCAT) {
        if (k + 3 < KS) {
            v = *(const float4*)(A + row * (size_t)KS + k);
        } else {
            float* pv = (float*)&v;
#pragma unroll
            for (int c = 0; c < 4; c++) {
                int kk = k + c;
                if (kk < KS)      pv[c] = A[row * (size_t)KS + kk];
                else if (kk < K)  pv[c] = A2[row * (size_t)(K - KS) + (kk - KS)];
            }
        }
    } else {
        if (k + 3 < K) {
            v = *(const float4*)(A + row * (size_t)K + k);
        } else {
            float* pv = (float*)&v;
#pragma unroll
            for (int c = 0; c < 4; c++)
                if (k + c < K) pv[c] = A[row * (size_t)K + k + c];
        }
    }
    return v;
}

__device__ __forceinline__ float4 loadW4(const float* __restrict__ W,
                                         int gn, int k, int K, int N)
{
    float4 v = make_float4(0.f, 0.f, 0.f, 0.f);
    if (gn < N) {
        if ((K & 3) == 0 && k + 3 < K) {
            v = *(const float4*)(W + (size_t)gn * (size_t)K + k);
        } else {
            float* pv = (float*)&v;
#pragma unroll
            for (int c = 0; c < 4; c++)
                if (k + c < K) pv[c] = W[(size_t)gn * (size_t)K + k + c];
        }
    }
    return v;
}

template<int ACT, int CONCAT>
__global__ __launch_bounds__(256, 2) void gemm_kernel(
    const float* __restrict__ A, const float* __restrict__ A2,
    int K, int KS,
    const float* __restrict__ W, const float* __restrict__ bias,
    float* __restrict__ C, int N)
{
    __shared__ float As[2][GBK * ASTR];   // As[s][kk][r]   (transposed)
    __shared__ float Ws[2][GBK * WSTR];   // Ws[s][kk][n]

    const int row0 = blockIdx.x * GBM;
    const int col0 = blockIdx.y * GBN;
    const int tid = threadIdx.x;
    const int tx = tid & 15;     // 4 cols each
    const int ty = tid >> 4;     // 8 rows each (4 row-pairs)

    // Loader mapping: kq = k-quad within tile, rA = row/col index
    const int kq = tid & 3;      // 0..3 -> k offset kq*4
    const int rA = tid >> 2;     // 0..63

    ull acc[4][4];
#pragma unroll
    for (int i = 0; i < 4; i++)
#pragma unroll
        for (int j = 0; j < 4; j++) acc[i][j] = 0ull;

    float4 la0, la1, lw;

    const int nT = (K + GBK - 1) / GBK;

    // Prologue: tile 0 -> buffer 0
    la0 = loadA4<CONCAT>(A, A2, (size_t)(row0 + rA),      kq * 4, K, KS);
    la1 = loadA4<CONCAT>(A, A2, (size_t)(row0 + rA + 64), kq * 4, K, KS);
    lw  = loadW4(W, col0 + rA, kq * 4, K, N);
    {
        As[0][(kq * 4 + 0) * ASTR + rA]      = la0.x;
        As[0][(kq * 4 + 1) * ASTR + rA]      = la0.y;
        As[0][(kq * 4 + 2) * ASTR + rA]      = la0.z;
        As[0][(kq * 4 + 3) * ASTR + rA]      = la0.w;
        As[0][(kq * 4 + 0) * ASTR + rA + 64] = la1.x;
        As[0][(kq * 4 + 1) * ASTR + rA + 64] = la1.y;
        As[0][(kq * 4 + 2) * ASTR + rA + 64] = la1.z;
        As[0][(kq * 4 + 3) * ASTR + rA + 64] = la1.w;
        Ws[0][(kq * 4 + 0) * WSTR + rA] = lw.x;
        Ws[0][(kq * 4 + 1) * WSTR + rA] = lw.y;
        Ws[0][(kq * 4 + 2) * WSTR + rA] = lw.z;
        Ws[0][(kq * 4 + 3) * WSTR + rA] = lw.w;
    }
    __syncthreads();

    int p = 0;
    for (int t = 0; t < nT; t++) {
        // Issue LDGs for next tile first (compute below hides their latency)
        if (t + 1 < nT) {
            int k = (t + 1) * GBK + kq * 4;
            la0 = loadA4<CONCAT>(A, A2, (size_t)(row0 + rA),      k, K, KS);
            la1 = loadA4<CONCAT>(A, A2, (size_t)(row0 + rA + 64), k, K, KS);
            lw  = loadW4(W, col0 + rA, k, K, N);
        }

        // Compute on buffer p
        const float* Ab = As[p];
        const float* Wb = Ws[p];
#pragma unroll
        for (int kk = 0; kk < GBK; kk++) {
            const ull* ap = (const ull*)(Ab + kk * ASTR + ty * 8);
            ull a2[4];
#pragma unroll
            for (int i = 0; i < 4; i++) a2[i] = ap[i];
            const float4 wv = *(const float4*)(Wb + kk * WSTR + tx * 4);
            ull w2[4];
            w2[0] = pack2(wv.x, wv.x);
            w2[1] = pack2(wv.y, wv.y);
            w2[2] = pack2(wv.z, wv.z);
            w2[3] = pack2(wv.w, wv.w);
#pragma unroll
            for (int i = 0; i < 4; i++)
#pragma unroll
                for (int j = 0; j < 4; j++) fma2(acc[i][j], a2[i], w2[j]);
        }

        // Store next tile into the other buffer
        if (t + 1 < nT) {
            int s = p ^ 1;
            As[s][(kq * 4 + 0) * ASTR + rA]      = la0.x;
            As[s][(kq * 4 + 1) * ASTR + rA]      = la0.y;
            As[s][(kq * 4 + 2) * ASTR + rA]      = la0.z;
            As[s][(kq * 4 + 3) * ASTR + rA]      = la0.w;
            As[s][(kq * 4 + 0) * ASTR + rA + 64] = la1.x;
            As[s][(kq * 4 + 1) * ASTR + rA + 64] = la1.y;
            As[s][(kq * 4 + 2) * ASTR + rA + 64] = la1.z;
            As[s][(kq * 4 + 3) * ASTR + rA + 64] = la1.w;
            Ws[s][(kq * 4 + 0) * WSTR + rA] = lw.x;
            Ws[s][(kq * 4 + 1) * WSTR + rA] = lw.y;
            Ws[s][(kq * 4 + 2) * WSTR + rA] = lw.z;
            Ws[s][(kq * 4 + 3) * WSTR + rA] = lw.w;
            __syncthreads();
        }
        p ^= 1;
    }

    // Epilogue: bias + activation + vectorized stores
    const int gc0 = col0 + tx * 4;
    float bv[4];
#pragma unroll
    for (int j = 0; j < 4; j++) bv[j] = (gc0 + j < N) ? bias[gc0 + j] : 0.f;

#pragma unroll
    for (int i = 0; i < 4; i++) {
        float vlo[4], vhi[4];
#pragma unroll
        for (int j = 0; j < 4; j++) {
            float lo, hi;
            unpack2(acc[i][j], lo, hi);
            lo += bv[j]; hi += bv[j];
            if (ACT) { lo = elu_f(lo); hi = elu_f(hi); }
            vlo[j] = lo; vhi[j] = hi;
        }
        size_t gr0 = (size_t)(row0 + ty * 8 + 2 * i);
        if (gc0 + 3 < N) {
            *(float4*)(C + gr0 * (size_t)N + gc0)       = make_float4(vlo[0], vlo[1], vlo[2], vlo[3]);
            *(float4*)(C + (gr0 + 1) * (size_t)N + gc0) = make_float4(vhi[0], vhi[1], vhi[2], vhi[3]);
        } else {
#pragma unroll
            for (int j = 0; j < 4; j++) {
                if (gc0 + j < N) {
                    C[gr0 * (size_t)N + gc0 + j]       = vlo[j];
                    C[(gr0 + 1) * (size_t)N + gc0 + j] = vhi[j];
                }
            }
        }
    }
}

// ---------------------------------------------------------------------------
// Recurrent scan: 128 persistent blocks = 16 batch-chunks(32) x 8 m-chunks(25).
// 128 threads (4 full warps). Whh slice (padded 80 rows x 200) in SMEM for all
// 256 steps. GX operands prefetched into registers before the mini-GEMM.
// Grid-wide step sync: release-atomic arrive + acquire-load spin.
// ---------------------------------------------------------------------------
#define SC_C   8
#define SC_R   16
#define SC_MC  25
#define SC_BC  32
#define SC_ROWS  75
#define SC_ROWSP 80
#define SC_THREADS 128
#define SC_SMEM_FLOATS (SC_ROWSP*200 + SC_BC*200 + SC_ROWSP*SC_BC + G3)

__global__ void init_bar_kernel() { g_bar = 0u; }

__global__ __launch_bounds__(SC_THREADS) void scan_kernel(
    const float* __restrict__ GX, const float* __restrict__ Whh,
    const float* __restrict__ bhh, const float* __restrict__ in_state,
    const unsigned char* __restrict__ reset, float* __restrict__ states)
{
    extern __shared__ float sm[];
    float* sW  = sm;                            // [80][200] Whh slice (persistent)
    float* sH  = sW + SC_ROWSP * 200;           // [32][200] h for this batch chunk
    float* sGH = sH + SC_BC * 200;              // [80][32]  gh results
    float* sBH = sGH + SC_ROWSP * SC_BC;        // [600]     bhh

    const int c   = blockIdx.x & 7;
    const int r   = blockIdx.x >> 3;
    const int tid = threadIdx.x;
    const int rg  = tid >> 3;   // 0..15 -> 5 gh-rows each (rows 75..79 padded)
    const int bg  = tid & 7;    // 0..7  -> 4 batch cols each
    const unsigned int nb = gridDim.x;

    // Load Whh slice once (padded rows zero):
    // local row lr -> gate g=lr/25, j=lr%25 -> global row g*200 + c*25 + j
    for (int idx = tid; idx < SC_ROWSP * 200; idx += SC_THREADS) {
        int lr = idx / 200, k = idx % 200;
        float v = 0.f;
        if (lr < SC_ROWS) {
            int g = lr / SC_MC, j = lr % SC_MC;
            int grow = g * 200 + c * SC_MC + j;
            v = Whh[(size_t)grow * 200 + k];
        }
        sW[idx] = v;
    }
    for (int idx = tid; idx < G3; idx += SC_THREADS) sBH[idx] = bhh[idx];

    for (int t = 0; t < T_STEPS; t++) {
        const float* hsrc = (t == 0) ? in_state
                                     : (states + (size_t)(t - 1) * B_DIM * M_DIM);
        // load h (64-bit loads, k-pairs)
        for (int idx = tid; idx < SC_BC * 100; idx += SC_THREADS) {
            int bl = idx / 100, kp = idx % 100;
            int b = r * SC_BC + bl;
            ull v = *(const ull*)(hsrc + (size_t)b * 200 + kp * 2);
            if (reset[t * B_DIM + b]) v = 0ull;
            *(ull*)(sH + bl * 200 + kp * 2) = v;
        }

        // Prefetch GX + bias for this step's elementwise (hidden under GEMM)
        float pxr[7], pxz[7], pxn[7];
        {
            size_t gbase = (size_t)(t * B_DIM) * G3;
#pragma unroll
            for (int q = 0; q < 7; q++) {
                int idx = tid + q * SC_THREADS;
                if (idx < SC_MC * SC_BC) {
                    int bl = idx / SC_MC, j = idx % SC_MC;
                    int b = r * SC_BC + bl;
                    int m = c * SC_MC + j;
                    size_t gxi = gbase + (size_t)b * G3 + m;
                    pxr[q] = GX[gxi];
                    pxz[q] = GX[gxi + 200];
                    pxn[q] = GX[gxi + 400];
                } else { pxr[q] = pxz[q] = pxn[q] = 0.f; }
            }
        }
        __syncthreads();

        // mini-GEMM: gh[80,32] = Whh_slice[80,200] @ h[32,200]^T (f32x2 over K)
        ull acc[5][4];
#pragma unroll
        for (int i = 0; i < 5; i++)
#pragma unroll
            for (int j = 0; j < 4; j++) acc[i][j] = 0ull;

#pragma unroll 2
        for (int k = 0; k < 200; k += 4) {
            ull w0[5], w1[5], h0[4], h1[4];
#pragma unroll
            for (int i = 0; i < 5; i++) {
                const ull* wp = (const ull*)(sW + (rg * 5 + i) * 200 + k);
                w0[i] = wp[0]; w1[i] = wp[1];
            }
#pragma unroll
            for (int j = 0; j < 4; j++) {
                const ull* hp = (const ull*)(sH + (bg * 4 + j) * 200 + k);
                h0[j] = hp[0]; h1[j] = hp[1];
            }
#pragma unroll
            for (int i = 0; i < 5; i++)
#pragma unroll
                for (int j = 0; j < 4; j++) {
                    fma2(acc[i][j], w0[i], h0[j]);
                    fma2(acc[i][j], w1[i], h1[j]);
                }
        }
#pragma unroll
        for (int i = 0; i < 5; i++)
#pragma unroll
            for (int j = 0; j < 4; j++) {
                float lo, hi;
                unpack2(acc[i][j], lo, hi);
                sGH[(rg * 5 + i) * SC_BC + bg * 4 + j] = lo + hi;
            }
        __syncthreads();

        // GRU elementwise for (25 m x 32 b) of this block
#pragma unroll
        for (int q = 0; q < 7; q++) {
            int idx = tid + q * SC_THREADS;
            if (idx < SC_MC * SC_BC) {
                int bl = idx / SC_MC, j = idx % SC_MC;
                int b = r * SC_BC + bl;
                int m = c * SC_MC + j;
                float hr = sGH[j * SC_BC + bl]               + sBH[m];
                float hz = sGH[(SC_MC + j) * SC_BC + bl]     + sBH[200 + m];
                float hn = sGH[(2 * SC_MC + j) * SC_BC + bl] + sBH[400 + m];
                float rgate = sigm_f(pxr[q] + hr);
                float z     = sigm_f(pxz[q] + hz);
                float n     = tanhf(pxn[q] + rgate * hn);
                float hp    = sH[bl * 200 + m];
                float hnew  = (1.f - z) * n + z * hp;
                states[(size_t)t * B_DIM * M_DIM + (size_t)b * M_DIM + m] = hnew;
            }
        }

        // Grid barrier: release arrive, acquire spin (orders the STG above)
        __syncthreads();
        if (tid == 0) {
            unsigned int old;
            asm volatile("atom.add.release.gpu.global.u32 %0, [%1], %2;"
                         : "=r"(old) : "l"(&g_bar), "r"(1u) : "memory");
            unsigned int target = nb * (unsigned int)(t + 1);
            unsigned int v;
            do {
                asm volatile("ld.acquire.gpu.global.u32 %0, [%1];"
                             : "=r"(v) : "l"(&g_bar) : "memory");
            } while (v < target);
        }
        __syncthreads();
    }
}

// ---------------------------------------------------------------------------
// Sample head: partitionable threefry (counter = linear index), bits = o0^o1.
// ---------------------------------------------------------------------------
__global__ void sample_kernel(const float* __restrict__ posts_last,
                              float* __restrict__ out)
{
    int i = blockIdx.x * blockDim.x + threadIdx.x;
    const int NTOT = B_DIM * S_DIM;      // 15360
    if (i >= NTOT) return;

    uint32_t x0 = 0u, x1 = (uint32_t)i;
    const uint32_t ks0 = 0u, ks1 = 42u, ks2 = 0u ^ 42u ^ 0x1BD11BDAu;
    x0 += ks0; x1 += ks1;
#define TF_RND(rot) { x0 += x1; x1 = (x1 << (rot)) | (x1 >> (32 - (rot))); x1 ^= x0; }
    TF_RND(13) TF_RND(15) TF_RND(26) TF_RND(6)   x0 += ks1; x1 += ks2 + 1u;
    TF_RND(17) TF_RND(29) TF_RND(16) TF_RND(24)  x0 += ks2; x1 += ks0 + 2u;
    TF_RND(13) TF_RND(15) TF_RND(26) TF_RND(6)   x0 += ks0; x1 += ks1 + 3u;
    TF_RND(17) TF_RND(29) TF_RND(16) TF_RND(24)  x0 += ks1; x1 += ks2 + 4u;
    TF_RND(13) TF_RND(15) TF_RND(26) TF_RND(6)   x0 += ks2; x1 += ks0 + 5u;
#undef TF_RND
    uint32_t bits = x0 ^ x1;

    float f = __uint_as_float((bits >> 9) | 0x3F800000u) - 1.0f;
    const float lo = -0.99999994f;
    float u = fmaxf(lo, f * 2.0f + lo);
    float noise = 1.41421356f * erfinvf(u);

    int b = i / S_DIM, s = i % S_DIM;
    float mean = posts_last[(size_t)b * 60 + s];
    float sraw = posts_last[(size_t)b * 60 + 30 + s];
    float stdv = fmaxf(sraw, 0.f) + log1pf(expf(-fabsf(sraw))) + 0.1f; // softplus + MIN_STD
    out[i] = mean + stdv * noise;
}

// ---------------------------------------------------------------------------
extern "C" void kernel_launch(void* const* d_in, const int* in_sizes, int n_in,
                              void* d_out, int out_size)
{
    const float* embed    = (const float*)d_in[0];
    const float* action   = (const float*)d_in[1];
    const unsigned char* reset = (const unsigned char*)d_in[2];
    const float* in_state = (const float*)d_in[3];
    const float* W1 = (const float*)d_in[4];
    const float* b1 = (const float*)d_in[5];
    const float *Wih, *bih, *Whh, *bhh;
    if (in_sizes[7] == 600) {          // dict order: Wih, bih, Whh, bhh
        Wih = (const float*)d_in[6]; bih = (const float*)d_in[7];
        Whh = (const float*)d_in[8]; bhh = (const float*)d_in[9];
    } else {                           // signature order: Wih, Whh, bih, bhh
        Wih = (const float*)d_in[6]; Whh = (const float*)d_in[7];
        bih = (const float*)d_in[8]; bhh = (const float*)d_in[9];
    }
    const float* W2 = (const float*)d_in[10];
    const float* b2 = (const float*)d_in[11];
    const float* W3 = (const float*)d_in[12];
    const float* b3 = (const float*)d_in[13];

    float* out    = (float*)d_out;
    float* sample = out;                                  // [512,30]
    float* states = out + (size_t)B_DIM * S_DIM;          // [256,512,200]
    float* posts  = states + (size_t)T_STEPS * B_DIM * M_DIM; // [256,512,60]

    float* Xbuf; cudaGetSymbolAddress((void**)&Xbuf, g_X);
    float* GXbuf; cudaGetSymbolAddress((void**)&GXbuf, g_GX);

    // K1: X = elu([embed,action] @ W1^T + b1)   [131072,263]x[263,200]
    gemm_kernel<1, 1><<<dim3(TB / 128, 4), 256>>>(
        embed, action, EA_DIM, E_DIM, W1, b1, Xbuf, H_DIM);

    // K2: GX = X @ Wih^T + bih                  [131072,200]x[200,600]
    gemm_kernel<0, 0><<<dim3(TB / 128, 10), 256>>>(
        Xbuf, nullptr, H_DIM, 0, Wih, bih, GXbuf, G3);

    // K3: recurrent scan -> states
    init_bar_kernel<<<1, 1>>>();
    cudaFuncSetAttribute(scan_kernel,
                         cudaFuncAttributeMaxDynamicSharedMemorySize,
                         SC_SMEM_FLOATS * (int)sizeof(float));
    scan_kernel<<<SC_C * SC_R, SC_THREADS, SC_SMEM_FLOATS * sizeof(float)>>>(
        GXbuf, Whh, bhh, in_state, reset, states);

    // K4: P1 = elu(states @ W2^T + b2)  (reuse g_X)
    gemm_kernel<1, 0><<<dim3(TB / 128, 4), 256>>>(
        states, nullptr, M_DIM, 0, W2, b2, Xbuf, H_DIM);

    // K5: posts = P1 @ W3^T + b3
    gemm_kernel<0, 0><<<dim3(TB / 128, 1), 256>>>(
        Xbuf, nullptr, H_DIM, 0, W3, b3, posts, 2 * S_DIM);

    // K6: sample from posts[-1] with partitionable-threefry noise
    const float* posts_last = posts + (size_t)(T_STEPS - 1) * B_DIM * 2 * S_DIM;
    sample_kernel<<<(B_DIM * S_DIM + 255) / 256, 256>>>(posts_last, sample);
}

// round 8
// speedup vs baseline: 1.3260x; 1.0055x over previous
#include <cuda_runtime.h>
#include <cstdint>
#include <cstddef>

// Problem dims
#define T_STEPS 256
#define B_DIM   512
#define E_DIM   256
#define A_DIM   7
#define M_DIM   200
#define S_DIM   30
#define H_DIM   200
#define EA_DIM  263
#define G3      600
#define TB      131072   // T*B

typedef unsigned long long ull;

// Scratch (static device arrays: allocation-free rule)
__device__ float g_X[(size_t)TB * 200];   // X, later reused as P1
__device__ float g_GX[(size_t)TB * 600];  // precomputed input-side GRU gates
__device__ unsigned int g_flags[128];     // per-block epoch flags (scan barrier)

__device__ __forceinline__ float elu_f(float x) { return x > 0.f ? x : expm1f(x); }
__device__ __forceinline__ float sigm_f(float x) { return 1.f / (1.f + expf(-x)); }

// Packed f32x2 helpers (Blackwell FFMA2)
__device__ __forceinline__ void fma2(ull& d, ull a, ull b) {
    asm("fma.rn.f32x2 %0, %1, %2, %3;" : "=l"(d) : "l"(a), "l"(b), "l"(d));
}
__device__ __forceinline__ ull pack2(float x, float y) {
    ull r;
    asm("mov.b64 %0, {%1, %2};" : "=l"(r)
        : "r"(__float_as_uint(x)), "r"(__float_as_uint(y)));
    return r;
}
__device__ __forceinline__ void unpack2(ull v, float& lo, float& hi) {
    unsigned int a, b;
    asm("mov.b64 {%0, %1}, %2;" : "=r"(a), "=r"(b) : "l"(v));
    lo = __uint_as_float(a); hi = __uint_as_float(b);
}

// ---------------------------------------------------------------------------
// f32x2 tiled GEMM with 2-stage smem double buffer (identical to R5).
// C[rows,N] = act(A[rows,K] @ W[N,K]^T + bias)
// ---------------------------------------------------------------------------
#define GBM 128
#define GBN 64
#define GBK 16
#define ASTR 132
#define WSTR 68

template<int CONCAT>
__device__ __forceinline__ float4 loadA4(const float* __restrict__ A,
                                         const float* __restrict__ A2,
                                         size_t row, int k, int K, int KS)
{
    float4 v = make_float4(0.f, 0.f, 0.f, 0.f);
    if (CONCAT) {
        if (k + 3 < KS) {
            v = *(const float4*)(A + row * (size_t)KS + k);
        } else {
            float* pv = (float*)&v;
#pragma unroll
            for (int c = 0; c < 4; c++) {
                int kk = k + c;
                if (kk < KS)      pv[c] = A[row * (size_t)KS + kk];
                else if (kk < K)  pv[c] = A2[row * (size_t)(K - KS) + (kk - KS)];
            }
        }
    } else {
        if (k + 3 < K) {
            v = *(const float4*)(A + row * (size_t)K + k);
        } else {
            float* pv = (float*)&v;
#pragma unroll
            for (int c = 0; c < 4; c++)
                if (k + c < K) pv[c] = A[row * (size_t)K + k + c];
        }
    }
    return v;
}

__device__ __forceinline__ float4 loadW4(const float* __restrict__ W,
                                         int gn, int k, int K, int N)
{
    float4 v = make_float4(0.f, 0.f, 0.f, 0.f);
    if (gn < N) {
        if ((K & 3) == 0 && k + 3 < K) {
            v = *(const float4*)(W + (size_t)gn * (size_t)K + k);
        } else {
            float* pv = (float*)&v;
#pragma unroll
            for (int c = 0; c < 4; c++)
                if (k + c < K) pv[c] = W[(size_t)gn * (size_t)K + k + c];
        }
    }
    return v;
}

template<int ACT, int CONCAT>
__global__ __launch_bounds__(256, 2) void gemm_kernel(
    const float* __restrict__ A, const float* __restrict__ A2,
    int K, int KS,
    const float* __restrict__ W, const float* __restrict__ bias,
    float* __restrict__ C, int N)
{
    __shared__ float As[2][GBK * ASTR];
    __shared__ float Ws[2][GBK * WSTR];

    const int row0 = blockIdx.x * GBM;
    const int col0 = blockIdx.y * GBN;
    const int tid = threadIdx.x;
    const int tx = tid & 15;
    const int ty = tid >> 4;
    const int kq = tid & 3;
    const int rA = tid >> 2;

    ull acc[4][4];
#pragma unroll
    for (int i = 0; i < 4; i++)
#pragma unroll
        for (int j = 0; j < 4; j++) acc[i][j] = 0ull;

    float4 la0, la1, lw;
    const int nT = (K + GBK - 1) / GBK;

    la0 = loadA4<CONCAT>(A, A2, (size_t)(row0 + rA),      kq * 4, K, KS);
    la1 = loadA4<CONCAT>(A, A2, (size_t)(row0 + rA + 64), kq * 4, K, KS);
    lw  = loadW4(W, col0 + rA, kq * 4, K, N);
    {
        As[0][(kq * 4 + 0) * ASTR + rA]      = la0.x;
        As[0][(kq * 4 + 1) * ASTR + rA]      = la0.y;
        As[0][(kq * 4 + 2) * ASTR + rA]      = la0.z;
        As[0][(kq * 4 + 3) * ASTR + rA]      = la0.w;
        As[0][(kq * 4 + 0) * ASTR + rA + 64] = la1.x;
        As[0][(kq * 4 + 1) * ASTR + rA + 64] = la1.y;
        As[0][(kq * 4 + 2) * ASTR + rA + 64] = la1.z;
        As[0][(kq * 4 + 3) * ASTR + rA + 64] = la1.w;
        Ws[0][(kq * 4 + 0) * WSTR + rA] = lw.x;
        Ws[0][(kq * 4 + 1) * WSTR + rA] = lw.y;
        Ws[0][(kq * 4 + 2) * WSTR + rA] = lw.z;
        Ws[0][(kq * 4 + 3) * WSTR + rA] = lw.w;
    }
    __syncthreads();

    int p = 0;
    for (int t = 0; t < nT; t++) {
        if (t + 1 < nT) {
            int k = (t + 1) * GBK + kq * 4;
            la0 = loadA4<CONCAT>(A, A2, (size_t)(row0 + rA),      k, K, KS);
            la1 = loadA4<CONCAT>(A, A2, (size_t)(row0 + rA + 64), k, K, KS);
            lw  = loadW4(W, col0 + rA, k, K, N);
        }

        const float* Ab = As[p];
        const float* Wb = Ws[p];
#pragma unroll
        for (int kk = 0; kk < GBK; kk++) {
            const ull* ap = (const ull*)(Ab + kk * ASTR + ty * 8);
            ull a2[4];
#pragma unroll
            for (int i = 0; i < 4; i++) a2[i] = ap[i];
            const float4 wv = *(const float4*)(Wb + kk * WSTR + tx * 4);
            ull w2[4];
            w2[0] = pack2(wv.x, wv.x);
            w2[1] = pack2(wv.y, wv.y);
            w2[2] = pack2(wv.z, wv.z);
            w2[3] = pack2(wv.w, wv.w);
#pragma unroll
            for (int i = 0; i < 4; i++)
#pragma unroll
                for (int j = 0; j < 4; j++) fma2(acc[i][j], a2[i], w2[j]);
        }

        if (t + 1 < nT) {
            int s = p ^ 1;
            As[s][(kq * 4 + 0) * ASTR + rA]      = la0.x;
            As[s][(kq * 4 + 1) * ASTR + rA]      = la0.y;
            As[s][(kq * 4 + 2) * ASTR + rA]      = la0.z;
            As[s][(kq * 4 + 3) * ASTR + rA]      = la0.w;
            As[s][(kq * 4 + 0) * ASTR + rA + 64] = la1.x;
            As[s][(kq * 4 + 1) * ASTR + rA + 64] = la1.y;
            As[s][(kq * 4 + 2) * ASTR + rA + 64] = la1.z;
            As[s][(kq * 4 + 3) * ASTR + rA + 64] = la1.w;
            Ws[s][(kq * 4 + 0) * WSTR + rA] = lw.x;
            Ws[s][(kq * 4 + 1) * WSTR + rA] = lw.y;
            Ws[s][(kq * 4 + 2) * WSTR + rA] = lw.z;
            Ws[s][(kq * 4 + 3) * WSTR + rA] = lw.w;
            __syncthreads();
        }
        p ^= 1;
    }

    const int gc0 = col0 + tx * 4;
    float bv[4];
#pragma unroll
    for (int j = 0; j < 4; j++) bv[j] = (gc0 + j < N) ? bias[gc0 + j] : 0.f;

#pragma unroll
    for (int i = 0; i < 4; i++) {
        float vlo[4], vhi[4];
#pragma unroll
        for (int j = 0; j < 4; j++) {
            float lo, hi;
            unpack2(acc[i][j], lo, hi);
            lo += bv[j]; hi += bv[j];
            if (ACT) { lo = elu_f(lo); hi = elu_f(hi); }
            vlo[j] = lo; vhi[j] = hi;
        }
        size_t gr0 = (size_t)(row0 + ty * 8 + 2 * i);
        if (gc0 + 3 < N) {
            *(float4*)(C + gr0 * (size_t)N + gc0)       = make_float4(vlo[0], vlo[1], vlo[2], vlo[3]);
            *(float4*)(C + (gr0 + 1) * (size_t)N + gc0) = make_float4(vhi[0], vhi[1], vhi[2], vhi[3]);
        } else {
#pragma unroll
            for (int j = 0; j < 4; j++) {
                if (gc0 + j < N) {
                    C[gr0 * (size_t)N + gc0 + j]       = vlo[j];
                    C[(gr0 + 1) * (size_t)N + gc0 + j] = vhi[j];
                }
            }
        }
    }
}

// ---------------------------------------------------------------------------
// Recurrent scan: 128 persistent blocks = 16 batch-chunks(32) x 8 m-chunks(25).
// NEW: dependency-scoped epoch barrier — block (r,c) signals g_flags[bid] and
// waits only on the 8 flags of its own r-group (8 threads poll in parallel).
// GX prefetch for step t+1 happens between signal and wait (covers skew).
// ---------------------------------------------------------------------------
#define SC_C   8
#define SC_R   16
#define SC_MC  25
#define SC_BC  32
#define SC_ROWS  75
#define SC_ROWSP 80
#define SC_THREADS 128
#define SC_SMEM_FLOATS (SC_ROWSP*200 + SC_BC*200 + SC_ROWSP*SC_BC + G3)

__global__ void init_flags_kernel() { g_flags[threadIdx.x] = 0u; }

__global__ __launch_bounds__(SC_THREADS) void scan_kernel(
    const float* __restrict__ GX, const float* __restrict__ Whh,
    const float* __restrict__ bhh, const float* __restrict__ in_state,
    const unsigned char* __restrict__ reset, float* __restrict__ states)
{
    extern __shared__ float sm[];
    float* sW  = sm;
    float* sH  = sW + SC_ROWSP * 200;
    float* sGH = sH + SC_BC * 200;
    float* sBH = sGH + SC_ROWSP * SC_BC;

    const int c   = blockIdx.x & 7;
    const int r   = blockIdx.x >> 3;
    const int tid = threadIdx.x;
    const int rg  = tid >> 3;
    const int bg  = tid & 7;

    for (int idx = tid; idx < SC_ROWSP * 200; idx += SC_THREADS) {
        int lr = idx / 200, k = idx % 200;
        float v = 0.f;
        if (lr < SC_ROWS) {
            int g = lr / SC_MC, j = lr % SC_MC;
            int grow = g * 200 + c * SC_MC + j;
            v = Whh[(size_t)grow * 200 + k];
        }
        sW[idx] = v;
    }
    for (int idx = tid; idx < G3; idx += SC_THREADS) sBH[idx] = bhh[idx];

    // Prologue GX prefetch for t=0
    float pxr[7], pxz[7], pxn[7];
#pragma unroll
    for (int q = 0; q < 7; q++) {
        int idx = tid + q * SC_THREADS;
        if (idx < SC_MC * SC_BC) {
            int bl = idx / SC_MC, j = idx % SC_MC;
            int b = r * SC_BC + bl;
            int m = c * SC_MC + j;
            size_t gxi = (size_t)b * G3 + m;
            pxr[q] = GX[gxi];
            pxz[q] = GX[gxi + 200];
            pxn[q] = GX[gxi + 400];
        } else { pxr[q] = pxz[q] = pxn[q] = 0.f; }
    }

    for (int t = 0; t < T_STEPS; t++) {
        const float* hsrc = (t == 0) ? in_state
                                     : (states + (size_t)(t - 1) * B_DIM * M_DIM);
        for (int idx = tid; idx < SC_BC * 100; idx += SC_THREADS) {
            int bl = idx / 100, kp = idx % 100;
            int b = r * SC_BC + bl;
            ull v = *(const ull*)(hsrc + (size_t)b * 200 + kp * 2);
            if (reset[t * B_DIM + b]) v = 0ull;
            *(ull*)(sH + bl * 200 + kp * 2) = v;
        }
        __syncthreads();

        // mini-GEMM: gh[80,32] = Whh_slice[80,200] @ h[32,200]^T (f32x2 over K)
        ull acc[5][4];
#pragma unroll
        for (int i = 0; i < 5; i++)
#pragma unroll
            for (int j = 0; j < 4; j++) acc[i][j] = 0ull;

#pragma unroll 2
        for (int k = 0; k < 200; k += 4) {
            ull w0[5], w1[5], h0[4], h1[4];
#pragma unroll
            for (int i = 0; i < 5; i++) {
                const ull* wp = (const ull*)(sW + (rg * 5 + i) * 200 + k);
                w0[i] = wp[0]; w1[i] = wp[1];
            }
#pragma unroll
            for (int j = 0; j < 4; j++) {
                const ull* hp = (const ull*)(sH + (bg * 4 + j) * 200 + k);
                h0[j] = hp[0]; h1[j] = hp[1];
            }
#pragma unroll
            for (int i = 0; i < 5; i++)
#pragma unroll
                for (int j = 0; j < 4; j++) {
                    fma2(acc[i][j], w0[i], h0[j]);
                    fma2(acc[i][j], w1[i], h1[j]);
                }
        }
#pragma unroll
        for (int i = 0; i < 5; i++)
#pragma unroll
            for (int j = 0; j < 4; j++) {
                float lo, hi;
                unpack2(acc[i][j], lo, hi);
                sGH[(rg * 5 + i) * SC_BC + bg * 4 + j] = lo + hi;
            }
        __syncthreads();

        // GRU elementwise for (25 m x 32 b) of this block
#pragma unroll
        for (int q = 0; q < 7; q++) {
            int idx = tid + q * SC_THREADS;
            if (idx < SC_MC * SC_BC) {
                int bl = idx / SC_MC, j = idx % SC_MC;
                int b = r * SC_BC + bl;
                int m = c * SC_MC + j;
                float hr = sGH[j * SC_BC + bl]               + sBH[m];
                float hz = sGH[(SC_MC + j) * SC_BC + bl]     + sBH[200 + m];
                float hn = sGH[(2 * SC_MC + j) * SC_BC + bl] + sBH[400 + m];
                float rgate = sigm_f(pxr[q] + hr);
                float z     = sigm_f(pxz[q] + hz);
                float n     = tanhf(pxn[q] + rgate * hn);
                float hp    = sH[bl * 200 + m];
                float hnew  = (1.f - z) * n + z * hp;
                states[(size_t)t * B_DIM * M_DIM + (size_t)b * M_DIM + m] = hnew;
            }
        }

        if (t + 1 < T_STEPS) {
            // Publish: all states stores of this block happen-before the release
            __syncthreads();
            if (tid == 0) {
                asm volatile("st.release.gpu.global.u32 [%0], %1;"
                             :: "l"(g_flags + blockIdx.x), "r"((unsigned)(t + 1))
                             : "memory");
            }

            // Prefetch GX for step t+1 while peers catch up
            size_t gbase = (size_t)((t + 1) * B_DIM) * G3;
#pragma unroll
            for (int q = 0; q < 7; q++) {
                int idx = tid + q * SC_THREADS;
                if (idx < SC_MC * SC_BC) {
                    int bl = idx / SC_MC, j = idx % SC_MC;
                    int b = r * SC_BC + bl;
                    int m = c * SC_MC + j;
                    size_t gxi = gbase + (size_t)b * G3 + m;
                    pxr[q] = GX[gxi];
                    pxz[q] = GX[gxi + 200];
                    pxn[q] = GX[gxi + 400];
                }
            }

            // Wait only for the 8 blocks of our r-group (one flag per thread)
            if (tid < SC_C) {
                const unsigned int* fp = g_flags + (r << 3) + tid;
                unsigned int v;
                do {
                    asm volatile("ld.acquire.gpu.global.u32 %0, [%1];"
                                 : "=r"(v) : "l"(fp) : "memory");
                } while (v < (unsigned)(t + 1));
            }
            __syncthreads();
        }
    }
}

// ---------------------------------------------------------------------------
// Sample head: partitionable threefry (counter = linear index), bits = o0^o1.
// ---------------------------------------------------------------------------
__global__ void sample_kernel(const float* __restrict__ posts_last,
                              float* __restrict__ out)
{
    int i = blockIdx.x * blockDim.x + threadIdx.x;
    const int NTOT = B_DIM * S_DIM;
    if (i >= NTOT) return;

    uint32_t x0 = 0u, x1 = (uint32_t)i;
    const uint32_t ks0 = 0u, ks1 = 42u, ks2 = 0u ^ 42u ^ 0x1BD11BDAu;
    x0 += ks0; x1 += ks1;
#define TF_RND(rot) { x0 += x1; x1 = (x1 << (rot)) | (x1 >> (32 - (rot))); x1 ^= x0; }
    TF_RND(13) TF_RND(15) TF_RND(26) TF_RND(6)   x0 += ks1; x1 += ks2 + 1u;
    TF_RND(17) TF_RND(29) TF_RND(16) TF_RND(24)  x0 += ks2; x1 += ks0 + 2u;
    TF_RND(13) TF_RND(15) TF_RND(26) TF_RND(6)   x0 += ks0; x1 += ks1 + 3u;
    TF_RND(17) TF_RND(29) TF_RND(16) TF_RND(24)  x0 += ks1; x1 += ks2 + 4u;
    TF_RND(13) TF_RND(15) TF_RND(26) TF_RND(6)   x0 += ks2; x1 += ks0 + 5u;
#undef TF_RND
    uint32_t bits = x0 ^ x1;

    float f = __uint_as_float((bits >> 9) | 0x3F800000u) - 1.0f;
    const float lo = -0.99999994f;
    float u = fmaxf(lo, f * 2.0f + lo);
    float noise = 1.41421356f * erfinvf(u);

    int b = i / S_DIM, s = i % S_DIM;
    float mean = posts_last[(size_t)b * 60 + s];
    float sraw = posts_last[(size_t)b * 60 + 30 + s];
    float stdv = fmaxf(sraw, 0.f) + log1pf(expf(-fabsf(sraw))) + 0.1f;
    out[i] = mean + stdv * noise;
}

// ---------------------------------------------------------------------------
extern "C" void kernel_launch(void* const* d_in, const int* in_sizes, int n_in,
                              void* d_out, int out_size)
{
    const float* embed    = (const float*)d_in[0];
    const float* action   = (const float*)d_in[1];
    const unsigned char* reset = (const unsigned char*)d_in[2];
    const float* in_state = (const float*)d_in[3];
    const float* W1 = (const float*)d_in[4];
    const float* b1 = (const float*)d_in[5];
    const float *Wih, *bih, *Whh, *bhh;
    if (in_sizes[7] == 600) {          // dict order: Wih, bih, Whh, bhh
        Wih = (const float*)d_in[6]; bih = (const float*)d_in[7];
        Whh = (const float*)d_in[8]; bhh = (const float*)d_in[9];
    } else {                           // signature order: Wih, Whh, bih, bhh
        Wih = (const float*)d_in[6]; Whh = (const float*)d_in[7];
        bih = (const float*)d_in[8]; bhh = (const float*)d_in[9];
    }
    const float* W2 = (const float*)d_in[10];
    const float* b2 = (const float*)d_in[11];
    const float* W3 = (const float*)d_in[12];
    const float* b3 = (const float*)d_in[13];

    float* out    = (float*)d_out;
    float* sample = out;                                  // [512,30]
    float* states = out + (size_t)B_DIM * S_DIM;          // [256,512,200]
    float* posts  = states + (size_t)T_STEPS * B_DIM * M_DIM; // [256,512,60]

    float* Xbuf; cudaGetSymbolAddress((void**)&Xbuf, g_X);
    float* GXbuf; cudaGetSymbolAddress((void**)&GXbuf, g_GX);

    // K1: X = elu([embed,action] @ W1^T + b1)   [131072,263]x[263,200]
    gemm_kernel<1, 1><<<dim3(TB / 128, 4), 256>>>(
        embed, action, EA_DIM, E_DIM, W1, b1, Xbuf, H_DIM);

    // K2: GX = X @ Wih^T + bih                  [131072,200]x[200,600]
    gemm_kernel<0, 0><<<dim3(TB / 128, 10), 256>>>(
        Xbuf, nullptr, H_DIM, 0, Wih, bih, GXbuf, G3);

    // K3: recurrent scan -> states
    init_flags_kernel<<<1, 128>>>();
    cudaFuncSetAttribute(scan_kernel,
                         cudaFuncAttributeMaxDynamicSharedMemorySize,
                         SC_SMEM_FLOATS * (int)sizeof(float));
    scan_kernel<<<SC_C * SC_R, SC_THREADS, SC_SMEM_FLOATS * sizeof(float)>>>(
        GXbuf, Whh, bhh, in_state, reset, states);

    // K4: P1 = elu(states @ W2^T + b2)  (reuse g_X)
    gemm_kernel<1, 0><<<dim3(TB / 128, 4), 256>>>(
        states, nullptr, M_DIM, 0, W2, b2, Xbuf, H_DIM);

    // K5: posts = P1 @ W3^T + b3
    gemm_kernel<0, 0><<<dim3(TB / 128, 1), 256>>>(
        Xbuf, nullptr, H_DIM, 0, W3, b3, posts, 2 * S_DIM);

    // K6: sample from posts[-1] with partitionable-threefry noise
    const float* posts_last = posts + (size_t)(T_STEPS - 1) * B_DIM * 2 * S_DIM;
    sample_kernel<<<(B_DIM * S_DIM + 255) / 256, 256>>>(posts_last, sample);
}